// round 7
// baseline (speedup 1.0000x reference)
#include <cuda_runtime.h>
#include <math.h>

#define T_STEPS   8192
#define N_RES     2048
#define DIN       64
#define DOUT      64
#define NNZ_CAP   384          // 32 lanes x 12 slots (mean nnz/row ~205)
#define SLOTS     12
#define GRID_MAIN 64
#define ROWS_PER_CTA 32        // 2048 / 64
#define THREADS_MAIN 1024      // 32 warps, 1 warp per row
#define LEAK      0.3f
#define ONE_MINUS_LEAK 0.7f
#define NOISE_SCL 0.01f

// ---- device scratch (static; no allocation anywhere) ----
__device__ float    g_vals[(size_t)N_RES * NNZ_CAP];
__device__ int      g_cols[(size_t)N_RES * NNZ_CAP];
__device__ float    g_states[(size_t)T_STEPS * N_RES];       // 64 MB, streaming (readout only)
// self-signaling exchange: (value bits, step tag) pairs, double-buffered by parity
__device__ __align__(16) uint2 g_xch[2][GRID_MAIN][ROWS_PER_CTA];   // 32 KB

// ---- reset exchange tags (runs first on every graph replay) ----
__global__ void k_init() {
    int i = blockIdx.x * blockDim.x + threadIdx.x;
    if (i < 2 * GRID_MAIN * ROWS_PER_CTA) ((uint2*)g_xch)[i] = make_uint2(0u, 0u);
}

// ---- build bank-aware padded sparse rows: one warp per row ----
// lane l primarily owns columns with col%32 == l -> conflict-free smem gathers;
// overflow entries are redistributed into other lanes' free slots.
#define SPILL_CAP 128
__global__ void __launch_bounds__(256) k_build(const float* __restrict__ W) {
    __shared__ float sv[8][SPILL_CAP];
    __shared__ int   sc[8][SPILL_CAP];
    __shared__ int   sn[8];
    int wwarp = threadIdx.x >> 5;
    int lane  = threadIdx.x & 31;
    int row   = blockIdx.x * 8 + wwarp;
    if (row >= N_RES) return;
    if (lane == 0) sn[wwarp] = 0;
    __syncwarp();

    const float* wr = W + (size_t)row * N_RES;
    float* vd = g_vals + (size_t)row * NNZ_CAP;
    int*   cd = g_cols + (size_t)row * NNZ_CAP;

    int cnt = 0;
    for (int base = 0; base < N_RES / 32; base++) {
        int col = base * 32 + lane;
        float v = wr[col];
        if (v != 0.0f) {
            if (cnt < SLOTS) { vd[lane * SLOTS + cnt] = v; cd[lane * SLOTS + cnt] = col; cnt++; }
            else {
                int p = atomicAdd(&sn[wwarp], 1);
                if (p < SPILL_CAP) { sv[wwarp][p] = v; sc[wwarp][p] = col; }
            }
        }
    }
    __syncwarp();
    int freecnt = SLOTS - cnt;
    int pfx = freecnt;
    #pragma unroll
    for (int o = 1; o < 32; o <<= 1) {
        int nv = __shfl_up_sync(0xffffffffu, pfx, o);
        if (lane >= o) pfx += nv;
    }
    int excl = pfx - freecnt;
    int ns = sn[wwarp]; if (ns > SPILL_CAP) ns = SPILL_CAP;
    for (int k = 0; k < freecnt; k++) {
        int idx = excl + k;
        if (idx < ns) { vd[lane * SLOTS + cnt + k] = sv[wwarp][idx]; cd[lane * SLOTS + cnt + k] = sc[wwarp][idx]; }
        else          { vd[lane * SLOTS + cnt + k] = 0.0f;           cd[lane * SLOTS + cnt + k] = lane; }
    }
}

// ---- persistent recurrence: double-buffered state, one barrier per step ----
// compute(row, from s_cur) -> publish -> poll/import into s_nxt -> syncthreads -> swap
__global__ void __launch_bounds__(THREADS_MAIN, 1)
k_reservoir(const float* __restrict__ u,
            const float* __restrict__ noise,
            const float* __restrict__ W_in) {
    __shared__ float s_buf[2][N_RES];     // double-buffered state (16 KB)
    __shared__ float u_s[2][DIN];

    const int tid  = threadIdx.x;
    const int lane = tid & 31;
    const int w    = tid >> 5;
    const int row  = blockIdx.x * ROWS_PER_CTA + w;

    // park this row's bank-aligned sparse slice in registers for the whole run
    float4 v4[3]; int4 c4[3];
    {
        const float4* vp = (const float4*)(g_vals + (size_t)row * NNZ_CAP + lane * SLOTS);
        const int4*   cp = (const int4*)  (g_cols + (size_t)row * NNZ_CAP + lane * SLOTS);
        #pragma unroll
        for (int c = 0; c < 3; c++) { v4[c] = vp[c]; c4[c] = cp[c]; }
    }
    const float win0 = W_in[row * DIN + lane];
    const float win1 = W_in[row * DIN + 32 + lane];

    for (int i = tid; i < N_RES; i += THREADS_MAIN) s_buf[0][i] = 0.0f;
    if (tid < DIN) u_s[0][tid] = u[tid];
    float noise_cur = noise[row];
    float noise_next = 0.0f;
    __syncthreads();

    for (int t = 0; t < T_STEPS; t++) {
        const int buf = t & 1;                 // parity: smem buffer AND xch buffer
        const int tn  = (t + 1 < T_STEPS) ? t + 1 : t;
        const unsigned target = (unsigned)(t + 1);
        const float* s_cur = s_buf[buf];
        float*       s_nxt = s_buf[buf ^ 1];

        // prefetch next input vector (off critical path)
        if (tid < DIN) u_s[buf ^ 1][tid] = __ldg(&u[tn * DIN + tid]);

        // drive + conflict-free sparse gathers from current state
        float acc = fmaf(win0, u_s[buf][lane], win1 * u_s[buf][lane + 32]);
        #pragma unroll
        for (int c = 0; c < 3; c++) {
            acc = fmaf(v4[c].x, s_cur[c4[c].x], acc);
            acc = fmaf(v4[c].y, s_cur[c4[c].y], acc);
            acc = fmaf(v4[c].z, s_cur[c4[c].z], acc);
            acc = fmaf(v4[c].w, s_cur[c4[c].w], acc);
        }
        #pragma unroll
        for (int o = 16; o; o >>= 1) acc += __shfl_xor_sync(0xffffffffu, acc, o);

        // lane 0 publishes its row the moment it's ready (no barrier before this)
        if (lane == 0) {
            acc += NOISE_SCL * noise_cur;
            float snew = ONE_MINUS_LEAK * s_cur[row] + LEAK * tanhf(acc);
            asm volatile("st.volatile.global.v2.u32 [%0], {%1,%2};"
                         :: "l"(&g_xch[buf][blockIdx.x][w]),
                            "r"(__float_as_uint(snew)), "r"(target) : "memory");
            __stcs(&g_states[(size_t)t * N_RES + row], snew);      // streaming, for k_out
            noise_next = __ldcs(&noise[(size_t)tn * N_RES + row]); // prefetch after publish
        }
        noise_cur = noise_next;

        // immediately poll/import into the OTHER buffer (overlaps other warps' compute).
        // warp w pulls source CTAs w and w+32; matching tag in the same 8B pair
        // proves the value belongs to this step.
        {
            const uint2* p0 = &g_xch[buf][w][lane];
            const uint2* p1 = &g_xch[buf][w + 32][lane];
            uint2 d0, d1; unsigned ok0 = 0u, ok1 = 0u;
            do {
                if (!ok0) {
                    asm volatile("ld.volatile.global.v2.u32 {%0,%1}, [%2];"
                                 : "=r"(d0.x), "=r"(d0.y) : "l"(p0) : "memory");
                    ok0 = (d0.y == target);
                }
                if (!ok1) {
                    asm volatile("ld.volatile.global.v2.u32 {%0,%1}, [%2];"
                                 : "=r"(d1.x), "=r"(d1.y) : "l"(p1) : "memory");
                    ok1 = (d1.y == target);
                }
            } while (__any_sync(0xffffffffu, (ok0 & ok1) == 0u));
            s_nxt[w * 32 + lane]        = __uint_as_float(d0.x);
            s_nxt[(w + 32) * 32 + lane] = __uint_as_float(d1.x);
        }
        __syncthreads();          // s_nxt complete; the ONLY barrier in the step
    }
}

// ---- readout GEMM: out[T,64] = states @ w_out^T + b_out ----
#define KC 32
__global__ void __launch_bounds__(128, 2)
k_out(const float* __restrict__ w_out, const float* __restrict__ b_out,
      float* __restrict__ out) {
    __shared__ float sA[32][KC];
    __shared__ float sB[64][KC];
    const int tid = threadIdx.x;
    const int tx  = tid & 15;
    const int ty  = tid >> 4;
    const int t0  = blockIdx.x * 32;

    float acc[4][4];
    #pragma unroll
    for (int i = 0; i < 4; i++)
        #pragma unroll
        for (int j = 0; j < 4; j++) acc[i][j] = 0.0f;

    for (int k0 = 0; k0 < N_RES; k0 += KC) {
        #pragma unroll
        for (int it = 0; it < 2; it++) {
            int idx = tid + it * 128;
            int r = idx >> 3, kk = (idx & 7) * 4;
            *(float4*)&sA[r][kk] = *(const float4*)&g_states[(size_t)(t0 + r) * N_RES + k0 + kk];
        }
        #pragma unroll
        for (int it = 0; it < 4; it++) {
            int idx = tid + it * 128;
            int r = idx >> 3, kk = (idx & 7) * 4;
            *(float4*)&sB[r][kk] = *(const float4*)&w_out[(size_t)r * N_RES + k0 + kk];
        }
        __syncthreads();
        #pragma unroll
        for (int kk = 0; kk < KC; kk += 4) {
            float4 a[4], b[4];
            #pragma unroll
            for (int i = 0; i < 4; i++) a[i] = *(const float4*)&sA[ty * 4 + i][kk];
            #pragma unroll
            for (int j = 0; j < 4; j++) b[j] = *(const float4*)&sB[tx * 4 + j][kk];
            #pragma unroll
            for (int i = 0; i < 4; i++)
                #pragma unroll
                for (int j = 0; j < 4; j++) {
                    acc[i][j] = fmaf(a[i].x, b[j].x, acc[i][j]);
                    acc[i][j] = fmaf(a[i].y, b[j].y, acc[i][j]);
                    acc[i][j] = fmaf(a[i].z, b[j].z, acc[i][j]);
                    acc[i][j] = fmaf(a[i].w, b[j].w, acc[i][j]);
                }
        }
        __syncthreads();
    }
    #pragma unroll
    for (int i = 0; i < 4; i++)
        #pragma unroll
        for (int j = 0; j < 4; j++)
            out[(size_t)(t0 + ty * 4 + i) * DOUT + tx * 4 + j] = acc[i][j] + b_out[tx * 4 + j];
}

extern "C" void kernel_launch(void* const* d_in, const int* in_sizes, int n_in,
                              void* d_out, int out_size) {
    const float* u     = (const float*)d_in[0];
    const float* noise = (const float*)d_in[1];
    const float* W_in  = (const float*)d_in[2];
    const float* W     = (const float*)d_in[3];
    const float* w_out = (const float*)d_in[4];
    const float* b_out = (const float*)d_in[5];
    float* out = (float*)d_out;

    k_init<<<4, 1024>>>();
    k_build<<<N_RES / 8, 256>>>(W);
    k_reservoir<<<GRID_MAIN, THREADS_MAIN>>>(u, noise, W_in);
    k_out<<<T_STEPS / 32, 128>>>(w_out, b_out, out);
}

// round 10
// speedup vs baseline: 1.3179x; 1.3179x over previous
#include <cuda_runtime.h>
#include <math.h>

#define T_STEPS   8192
#define N_RES     2048
#define DIN       64
#define DOUT      64
#define NNZ_CAP   384          // 32 lanes x 12 slots (mean nnz/row ~205)
#define SLOTS     12
#define GRID_MAIN 64
#define ROWS_PER_CTA 32        // 2048 / 64
#define THREADS_MAIN 1024      // 32 warps, 1 warp per row
#define FLAG_STRIDE 32         // 128 B -> one L2 line per flag
#define LEAK      0.3f
#define ONE_MINUS_LEAK 0.7f
#define NOISE_SCL 0.01f

// ---- device scratch (static; no allocation anywhere) ----
__device__ float    g_vals[(size_t)N_RES * NNZ_CAP];
__device__ int      g_cols[(size_t)N_RES * NNZ_CAP];
__device__ __align__(128) float g_states[(size_t)T_STEPS * N_RES]; // 64 MB
__device__ __align__(128) unsigned g_flags[GRID_MAIN * FLAG_STRIDE];

// ---- reset barrier flags (runs first on every graph replay) ----
__global__ void k_init() {
    int i = blockIdx.x * blockDim.x + threadIdx.x;
    if (i < GRID_MAIN * FLAG_STRIDE) g_flags[i] = 0u;
}

// ---- build bank-aware padded sparse rows: one warp per row ----
// lane l primarily owns columns with col%32 == l -> conflict-free smem gathers;
// overflow entries are redistributed into other lanes' free slots.
#define SPILL_CAP 128
__global__ void __launch_bounds__(256) k_build(const float* __restrict__ W) {
    __shared__ float sv[8][SPILL_CAP];
    __shared__ int   sc[8][SPILL_CAP];
    __shared__ int   sn[8];
    int wwarp = threadIdx.x >> 5;
    int lane  = threadIdx.x & 31;
    int row   = blockIdx.x * 8 + wwarp;
    if (row >= N_RES) return;
    if (lane == 0) sn[wwarp] = 0;
    __syncwarp();

    const float* wr = W + (size_t)row * N_RES;
    float* vd = g_vals + (size_t)row * NNZ_CAP;
    int*   cd = g_cols + (size_t)row * NNZ_CAP;

    int cnt = 0;
    for (int base = 0; base < N_RES / 32; base++) {
        int col = base * 32 + lane;
        float v = wr[col];
        if (v != 0.0f) {
            if (cnt < SLOTS) { vd[lane * SLOTS + cnt] = v; cd[lane * SLOTS + cnt] = col; cnt++; }
            else {
                int p = atomicAdd(&sn[wwarp], 1);
                if (p < SPILL_CAP) { sv[wwarp][p] = v; sc[wwarp][p] = col; }
            }
        }
    }
    __syncwarp();
    int freecnt = SLOTS - cnt;
    int pfx = freecnt;
    #pragma unroll
    for (int o = 1; o < 32; o <<= 1) {
        int nv = __shfl_up_sync(0xffffffffu, pfx, o);
        if (lane >= o) pfx += nv;
    }
    int excl = pfx - freecnt;
    int ns = sn[wwarp]; if (ns > SPILL_CAP) ns = SPILL_CAP;
    for (int k = 0; k < freecnt; k++) {
        int idx = excl + k;
        if (idx < ns) { vd[lane * SLOTS + cnt + k] = sv[wwarp][idx]; cd[lane * SLOTS + cnt + k] = sc[wwarp][idx]; }
        else          { vd[lane * SLOTS + cnt + k] = 0.0f;           cd[lane * SLOTS + cnt + k] = lane; }
    }
}

// ---- persistent recurrence: R4 barrier + single cp.async.bulk state reload ----
__global__ void __launch_bounds__(THREADS_MAIN, 1)
k_reservoir(const float* __restrict__ u,
            const float* __restrict__ noise,
            const float* __restrict__ W_in) {
    __shared__ __align__(128) float s_smem[N_RES];   // 8 KB, refreshed by bulk copy
    __shared__ float u_s[2][DIN];
    __shared__ __align__(16) float stage[ROWS_PER_CTA];
    __shared__ __align__(8) unsigned long long mbar;

    const int tid  = threadIdx.x;
    const int lane = tid & 31;
    const int w    = tid >> 5;
    const int row  = blockIdx.x * ROWS_PER_CTA + w;

    // park this row's bank-aligned sparse slice in registers for the whole run
    float4 v4[3]; int4 c4[3];
    {
        const float4* vp = (const float4*)(g_vals + (size_t)row * NNZ_CAP + lane * SLOTS);
        const int4*   cp = (const int4*)  (g_cols + (size_t)row * NNZ_CAP + lane * SLOTS);
        #pragma unroll
        for (int c = 0; c < 3; c++) { v4[c] = vp[c]; c4[c] = cp[c]; }
    }
    const float win0 = W_in[row * DIN + lane];
    const float win1 = W_in[row * DIN + 32 + lane];

    unsigned mbar_addr;
    {
        unsigned long long tmp;
        asm ("cvta.to.shared.u64 %0, %1;" : "=l"(tmp) : "l"(&mbar));
        mbar_addr = (unsigned)tmp;
    }
    unsigned smem_dst;
    {
        unsigned long long tmp;
        asm ("cvta.to.shared.u64 %0, %1;" : "=l"(tmp) : "l"(s_smem));
        smem_dst = (unsigned)tmp;
    }

    for (int i = tid; i < N_RES; i += THREADS_MAIN) s_smem[i] = 0.0f;
    if (tid < DIN) u_s[0][tid] = u[tid];
    if (tid == 0) {
        asm volatile("mbarrier.init.shared.b64 [%0], 1;" :: "r"(mbar_addr) : "memory");
    }
    float noise_cur = noise[row];
    float noise_next = 0.0f;
    __syncthreads();

    for (int t = 0; t < T_STEPS; t++) {
        const int buf = t & 1;
        const int tn  = (t + 1 < T_STEPS) ? t + 1 : t;
        const unsigned target = (unsigned)(t + 1);

        // prefetch next input vector (off critical path)
        if (tid < DIN) u_s[buf ^ 1][tid] = __ldg(&u[tn * DIN + tid]);

        // drive + conflict-free sparse gathers from current state
        float acc = fmaf(win0, u_s[buf][lane], win1 * u_s[buf][lane + 32]);
        #pragma unroll
        for (int c = 0; c < 3; c++) {
            acc = fmaf(v4[c].x, s_smem[c4[c].x], acc);
            acc = fmaf(v4[c].y, s_smem[c4[c].y], acc);
            acc = fmaf(v4[c].z, s_smem[c4[c].z], acc);
            acc = fmaf(v4[c].w, s_smem[c4[c].w], acc);
        }
        #pragma unroll
        for (int o = 16; o; o >>= 1) acc += __shfl_xor_sync(0xffffffffu, acc, o);

        if (lane == 0) {
            acc += NOISE_SCL * noise_cur;
            stage[w] = ONE_MINUS_LEAK * s_smem[row] + LEAK * tanhf(acc);
            noise_next = __ldcs(&noise[(size_t)tn * N_RES + row]);
        }
        noise_cur = noise_next;
        __syncthreads();       // stage complete; ALL s_smem reads of step t done

        if (tid == 0) {
            // publish this CTA's 32 values (128 B contiguous) then release flag.
            // Same-thread release orders the data stores before the flag: no fence.
            float4* dst = (float4*)(g_states + (size_t)t * N_RES + blockIdx.x * ROWS_PER_CTA);
            const float4* sg = (const float4*)stage;
            #pragma unroll
            for (int i = 0; i < 8; i++) dst[i] = sg[i];
            asm volatile("st.release.gpu.u32 [%0], %1;"
                         :: "l"(&g_flags[blockIdx.x * FLAG_STRIDE]), "r"(target) : "memory");
        }

        // warp 0 (lowest arbiter priority) polls all 64 line-isolated flags
        if (w == 0) {
            const unsigned* f0 = &g_flags[lane * FLAG_STRIDE];
            const unsigned* f1 = &g_flags[(lane + 32) * FLAG_STRIDE];
            unsigned a, b; unsigned ok0 = 0u, ok1 = 0u;
            do {
                if (!ok0) {
                    asm volatile("ld.acquire.gpu.u32 %0, [%1];" : "=r"(a) : "l"(f0) : "memory");
                    ok0 = (a >= target);
                }
                if (!ok1) {
                    asm volatile("ld.acquire.gpu.u32 %0, [%1];" : "=r"(b) : "l"(f1) : "memory");
                    ok1 = (b >= target);
                }
            } while (__any_sync(0xffffffffu, (ok0 & ok1) == 0u));

            if (lane == 0) {
                // single bulk async copy: g_states row t (8 KB) -> s_smem.
                // No per-thread LSU cost; completion signaled on the mbarrier.
                asm volatile("fence.proxy.async;" ::: "memory");
                asm volatile("mbarrier.arrive.expect_tx.shared.b64 _, [%0], %1;"
                             :: "r"(mbar_addr), "r"((unsigned)(N_RES * 4)) : "memory");
                asm volatile("cp.async.bulk.shared::cta.global.mbarrier::complete_tx::bytes"
                             " [%0], [%1], %2, [%3];"
                             :: "r"(smem_dst), "l"(g_states + (size_t)t * N_RES),
                                "r"((unsigned)(N_RES * 4)), "r"(mbar_addr) : "memory");
            }
        }

        // everyone (incl. warp 0) parks on the mbarrier until the new state lands
        {
            const unsigned parity = (unsigned)(t & 1);
            unsigned done;
            asm volatile(
                "{\n\t.reg .pred p;\n\t"
                "mbarrier.try_wait.parity.acquire.cta.shared::cta.b64 p, [%1], %2;\n\t"
                "selp.b32 %0, 1, 0, p;\n\t}"
                : "=r"(done) : "r"(mbar_addr), "r"(parity) : "memory");
            if (!done) {
                asm volatile(
                    "{\n\t.reg .pred P1;\n\t"
                    "W_%=:\n\t"
                    "mbarrier.try_wait.parity.acquire.cta.shared::cta.b64 P1, [%0], %1, 0x989680;\n\t"
                    "@P1 bra.uni D_%=;\n\t"
                    "bra.uni W_%=;\n\t"
                    "D_%=:\n\t}"
                    :: "r"(mbar_addr), "r"(parity) : "memory");
            }
        }
        // all threads passed the same phase -> s_smem holds s_{t+1}; no extra barrier
    }
}

// ---- readout GEMM: out[T,64] = states @ w_out^T + b_out ----
// 16-row tiles -> 512 CTAs (~3.5/SM) for latency hiding
#define KC 32
__global__ void __launch_bounds__(128, 8)
k_out(const float* __restrict__ w_out, const float* __restrict__ b_out,
      float* __restrict__ out) {
    __shared__ float sA[16][KC];
    __shared__ float sB[64][KC];
    const int tid = threadIdx.x;
    const int tx  = tid & 15;      // 4 output cols each
    const int ty  = tid >> 4;      // 0..7 -> 2 output rows each
    const int t0  = blockIdx.x * 16;

    float acc[2][4];
    #pragma unroll
    for (int i = 0; i < 2; i++)
        #pragma unroll
        for (int j = 0; j < 4; j++) acc[i][j] = 0.0f;

    for (int k0 = 0; k0 < N_RES; k0 += KC) {
        {
            int r = tid >> 3, kk = (tid & 7) * 4;   // 128 float4 slots
            *(float4*)&sA[r][kk] = *(const float4*)&g_states[(size_t)(t0 + r) * N_RES + k0 + kk];
        }
        #pragma unroll
        for (int it = 0; it < 4; it++) {
            int idx = tid + it * 128;
            int r = idx >> 3, kk = (idx & 7) * 4;
            *(float4*)&sB[r][kk] = *(const float4*)&w_out[(size_t)r * N_RES + k0 + kk];
        }
        __syncthreads();
        #pragma unroll
        for (int kk = 0; kk < KC; kk += 4) {
            float4 a[2], b[4];
            #pragma unroll
            for (int i = 0; i < 2; i++) a[i] = *(const float4*)&sA[ty * 2 + i][kk];
            #pragma unroll
            for (int j = 0; j < 4; j++) b[j] = *(const float4*)&sB[tx * 4 + j][kk];
            #pragma unroll
            for (int i = 0; i < 2; i++)
                #pragma unroll
                for (int j = 0; j < 4; j++) {
                    acc[i][j] = fmaf(a[i].x, b[j].x, acc[i][j]);
                    acc[i][j] = fmaf(a[i].y, b[j].y, acc[i][j]);
                    acc[i][j] = fmaf(a[i].z, b[j].z, acc[i][j]);
                    acc[i][j] = fmaf(a[i].w, b[j].w, acc[i][j]);
                }
        }
        __syncthreads();
    }
    #pragma unroll
    for (int i = 0; i < 2; i++)
        #pragma unroll
        for (int j = 0; j < 4; j++)
            out[(size_t)(t0 + ty * 2 + i) * DOUT + tx * 4 + j] = acc[i][j] + b_out[tx * 4 + j];
}

extern "C" void kernel_launch(void* const* d_in, const int* in_sizes, int n_in,
                              void* d_out, int out_size) {
    const float* u     = (const float*)d_in[0];
    const float* noise = (const float*)d_in[1];
    const float* W_in  = (const float*)d_in[2];
    const float* W     = (const float*)d_in[3];
    const float* w_out = (const float*)d_in[4];
    const float* b_out = (const float*)d_in[5];
    float* out = (float*)d_out;

    k_init<<<2, 1024>>>();
    k_build<<<N_RES / 8, 256>>>(W);
    k_reservoir<<<GRID_MAIN, THREADS_MAIN>>>(u, noise, W_in);
    k_out<<<T_STEPS / 16, 128>>>(w_out, b_out, out);
}

// round 11
// speedup vs baseline: 2.8006x; 2.1250x over previous
#include <cuda_runtime.h>
#include <math.h>

#define T_STEPS   8192
#define N_RES     2048
#define DIN       64
#define DOUT      64
#define NNZ_CAP   384          // 32 lanes x 12 slots (mean nnz/row ~205)
#define SLOTS     12
#define GRID_MAIN 64
#define ROWS_PER_CTA 32        // 2048 / 64
#define THREADS_MAIN 1024      // 32 warps, 1 warp per row
#define PUB_CHUNKS 11          // ceil(32/3) chunks of (3 floats + tag)
#define PUB_STRIDE 16          // uint4 slots per CTA block -> 256 B aligned
#define N_IMP (GRID_MAIN * PUB_CHUNKS)   // 704 importer threads
#define LEAK      0.3f
#define ONE_MINUS_LEAK 0.7f
#define NOISE_SCL 0.01f

// ---- device scratch (static; no allocation anywhere) ----
__device__ float    g_vals[(size_t)N_RES * NNZ_CAP];
__device__ int      g_cols[(size_t)N_RES * NNZ_CAP];
__device__ __align__(128) float g_states[(size_t)T_STEPS * N_RES]; // 64 MB (readout)
// self-validating publish buffer: 16B chunks = {f0,f1,f2,tag}, parity double-buffered
__device__ __align__(128) uint4 g_pub[2][GRID_MAIN][PUB_STRIDE];   // 32 KB

// ---- reset publish tags (runs first on every graph replay) ----
__global__ void k_init() {
    int i = blockIdx.x * blockDim.x + threadIdx.x;
    if (i < 2 * GRID_MAIN * PUB_STRIDE) ((uint4*)g_pub)[i] = make_uint4(0u, 0u, 0u, 0u);
}

// ---- build bank-aware padded sparse rows: one warp per row ----
// lane l primarily owns columns with col%32 == l -> conflict-free smem gathers;
// overflow entries are redistributed into other lanes' free slots.
#define SPILL_CAP 128
__global__ void __launch_bounds__(256) k_build(const float* __restrict__ W) {
    __shared__ float sv[8][SPILL_CAP];
    __shared__ int   sc[8][SPILL_CAP];
    __shared__ int   sn[8];
    int wwarp = threadIdx.x >> 5;
    int lane  = threadIdx.x & 31;
    int row   = blockIdx.x * 8 + wwarp;
    if (row >= N_RES) return;
    if (lane == 0) sn[wwarp] = 0;
    __syncwarp();

    const float* wr = W + (size_t)row * N_RES;
    float* vd = g_vals + (size_t)row * NNZ_CAP;
    int*   cd = g_cols + (size_t)row * NNZ_CAP;

    int cnt = 0;
    for (int base = 0; base < N_RES / 32; base++) {
        int col = base * 32 + lane;
        float v = wr[col];
        if (v != 0.0f) {
            if (cnt < SLOTS) { vd[lane * SLOTS + cnt] = v; cd[lane * SLOTS + cnt] = col; cnt++; }
            else {
                int p = atomicAdd(&sn[wwarp], 1);
                if (p < SPILL_CAP) { sv[wwarp][p] = v; sc[wwarp][p] = col; }
            }
        }
    }
    __syncwarp();
    int freecnt = SLOTS - cnt;
    int pfx = freecnt;
    #pragma unroll
    for (int o = 1; o < 32; o <<= 1) {
        int nv = __shfl_up_sync(0xffffffffu, pfx, o);
        if (lane >= o) pfx += nv;
    }
    int excl = pfx - freecnt;
    int ns = sn[wwarp]; if (ns > SPILL_CAP) ns = SPILL_CAP;
    for (int k = 0; k < freecnt; k++) {
        int idx = excl + k;
        if (idx < ns) { vd[lane * SLOTS + cnt + k] = sv[wwarp][idx]; cd[lane * SLOTS + cnt + k] = sc[wwarp][idx]; }
        else          { vd[lane * SLOTS + cnt + k] = 0.0f;           cd[lane * SLOTS + cnt + k] = lane; }
    }
}

// ---- persistent recurrence: tagged-chunk exchange, one L2 hop per step ----
__global__ void __launch_bounds__(THREADS_MAIN, 1)
k_reservoir(const float* __restrict__ u,
            const float* __restrict__ noise,
            const float* __restrict__ W_in) {
    __shared__ float s_smem[N_RES];                  // current state (8 KB)
    __shared__ float u_s[2][DIN];
    __shared__ __align__(16) float stage[ROWS_PER_CTA];

    const int tid  = threadIdx.x;
    const int lane = tid & 31;
    const int w    = tid >> 5;
    const int row  = blockIdx.x * ROWS_PER_CTA + w;

    // importer assignment (fixed for the whole run)
    const int imp_src   = tid / PUB_CHUNKS;          // source CTA
    const int imp_chunk = tid - imp_src * PUB_CHUNKS;
    const int imp_base  = imp_src * ROWS_PER_CTA + imp_chunk * 3;
    const int imp_cnt   = (imp_chunk == PUB_CHUNKS - 1) ? 2 : 3;
    const uint4* imp_p0 = &g_pub[0][imp_src][imp_chunk];
    const uint4* imp_p1 = &g_pub[1][imp_src][imp_chunk];

    // park this row's bank-aligned sparse slice in registers for the whole run
    float4 v4[3]; int4 c4[3];
    {
        const float4* vp = (const float4*)(g_vals + (size_t)row * NNZ_CAP + lane * SLOTS);
        const int4*   cp = (const int4*)  (g_cols + (size_t)row * NNZ_CAP + lane * SLOTS);
        #pragma unroll
        for (int c = 0; c < 3; c++) { v4[c] = vp[c]; c4[c] = cp[c]; }
    }
    const float win0 = W_in[row * DIN + lane];
    const float win1 = W_in[row * DIN + 32 + lane];

    for (int i = tid; i < N_RES; i += THREADS_MAIN) s_smem[i] = 0.0f;
    if (tid < DIN) u_s[0][tid] = u[tid];
    float noise_cur = noise[row];
    float noise_next = 0.0f;
    __syncthreads();

    for (int t = 0; t < T_STEPS; t++) {
        const int buf = t & 1;
        const int tn  = (t + 1 < T_STEPS) ? t + 1 : t;
        const unsigned target = (unsigned)(t + 1);

        // prefetch next input vector (off critical path)
        if (tid < DIN) u_s[buf ^ 1][tid] = __ldg(&u[tn * DIN + tid]);

        // drive + conflict-free sparse gathers from current state
        float acc = fmaf(win0, u_s[buf][lane], win1 * u_s[buf][lane + 32]);
        #pragma unroll
        for (int c = 0; c < 3; c++) {
            acc = fmaf(v4[c].x, s_smem[c4[c].x], acc);
            acc = fmaf(v4[c].y, s_smem[c4[c].y], acc);
            acc = fmaf(v4[c].z, s_smem[c4[c].z], acc);
            acc = fmaf(v4[c].w, s_smem[c4[c].w], acc);
        }
        #pragma unroll
        for (int o = 16; o; o >>= 1) acc += __shfl_xor_sync(0xffffffffu, acc, o);

        if (lane == 0) {
            acc += NOISE_SCL * noise_cur;
            stage[w] = ONE_MINUS_LEAK * s_smem[row] + LEAK * tanhf(acc);
            noise_next = __ldcs(&noise[(size_t)tn * N_RES + row]);
        }
        noise_cur = noise_next;
        __syncthreads();       // stage complete; ALL s_smem reads of step t done

        // ---- publish: 11 tagged 16B chunks (threads 0-10), states row (32-39) ----
        if (tid < PUB_CHUNKS) {
            int base = tid * 3;
            uint4 pkt;
            pkt.x = __float_as_uint(stage[base]);
            pkt.y = __float_as_uint(stage[(base + 1 < ROWS_PER_CTA) ? base + 1 : 0]);
            pkt.z = __float_as_uint(stage[(base + 2 < ROWS_PER_CTA) ? base + 2 : 0]);
            pkt.w = target;
            asm volatile("st.volatile.global.v4.u32 [%0], {%1,%2,%3,%4};"
                         :: "l"(&g_pub[buf][blockIdx.x][tid]),
                            "r"(pkt.x), "r"(pkt.y), "r"(pkt.z), "r"(pkt.w) : "memory");
        } else if (tid >= 32 && tid < 40) {
            int i = tid - 32;    // stream full CTA row to g_states for k_out
            ((float4*)(g_states + (size_t)t * N_RES + blockIdx.x * ROWS_PER_CTA))[i] =
                ((const float4*)stage)[i];
        }

        // ---- import == barrier: each of 704 threads spins on ONE chunk ----
        if (tid < N_IMP) {
            const uint4* p = buf ? imp_p1 : imp_p0;
            uint4 d;
            do {
                asm volatile("ld.volatile.global.v4.u32 {%0,%1,%2,%3}, [%4];"
                             : "=r"(d.x), "=r"(d.y), "=r"(d.z), "=r"(d.w)
                             : "l"(p) : "memory");
            } while (d.w != target);
            s_smem[imp_base] = __uint_as_float(d.x);
            if (imp_cnt > 1) s_smem[imp_base + 1] = __uint_as_float(d.y);
            if (imp_cnt > 2) s_smem[imp_base + 2] = __uint_as_float(d.z);
        }
        __syncthreads();       // s_{t+1} fully resident
    }
}

// ---- readout GEMM: out[T,64] = states @ w_out^T + b_out (R4-measured best) ----
#define KC 32
__global__ void __launch_bounds__(128, 2)
k_out(const float* __restrict__ w_out, const float* __restrict__ b_out,
      float* __restrict__ out) {
    __shared__ float sA[32][KC];
    __shared__ float sB[64][KC];
    const int tid = threadIdx.x;
    const int tx  = tid & 15;
    const int ty  = tid >> 4;
    const int t0  = blockIdx.x * 32;

    float acc[4][4];
    #pragma unroll
    for (int i = 0; i < 4; i++)
        #pragma unroll
        for (int j = 0; j < 4; j++) acc[i][j] = 0.0f;

    for (int k0 = 0; k0 < N_RES; k0 += KC) {
        #pragma unroll
        for (int it = 0; it < 2; it++) {
            int idx = tid + it * 128;
            int r = idx >> 3, kk = (idx & 7) * 4;
            *(float4*)&sA[r][kk] = *(const float4*)&g_states[(size_t)(t0 + r) * N_RES + k0 + kk];
        }
        #pragma unroll
        for (int it = 0; it < 4; it++) {
            int idx = tid + it * 128;
            int r = idx >> 3, kk = (idx & 7) * 4;
            *(float4*)&sB[r][kk] = *(const float4*)&w_out[(size_t)r * N_RES + k0 + kk];
        }
        __syncthreads();
        #pragma unroll
        for (int kk = 0; kk < KC; kk += 4) {
            float4 a[4], b[4];
            #pragma unroll
            for (int i = 0; i < 4; i++) a[i] = *(const float4*)&sA[ty * 4 + i][kk];
            #pragma unroll
            for (int j = 0; j < 4; j++) b[j] = *(const float4*)&sB[tx * 4 + j][kk];
            #pragma unroll
            for (int i = 0; i < 4; i++)
                #pragma unroll
                for (int j = 0; j < 4; j++) {
                    acc[i][j] = fmaf(a[i].x, b[j].x, acc[i][j]);
                    acc[i][j] = fmaf(a[i].y, b[j].y, acc[i][j]);
                    acc[i][j] = fmaf(a[i].z, b[j].z, acc[i][j]);
                    acc[i][j] = fmaf(a[i].w, b[j].w, acc[i][j]);
                }
        }
        __syncthreads();
    }
    #pragma unroll
    for (int i = 0; i < 4; i++)
        #pragma unroll
        for (int j = 0; j < 4; j++)
            out[(size_t)(t0 + ty * 4 + i) * DOUT + tx * 4 + j] = acc[i][j] + b_out[tx * 4 + j];
}

extern "C" void kernel_launch(void* const* d_in, const int* in_sizes, int n_in,
                              void* d_out, int out_size) {
    const float* u     = (const float*)d_in[0];
    const float* noise = (const float*)d_in[1];
    const float* W_in  = (const float*)d_in[2];
    const float* W     = (const float*)d_in[3];
    const float* w_out = (const float*)d_in[4];
    const float* b_out = (const float*)d_in[5];
    float* out = (float*)d_out;

    k_init<<<2, 1024>>>();
    k_build<<<N_RES / 8, 256>>>(W);
    k_reservoir<<<GRID_MAIN, THREADS_MAIN>>>(u, noise, W_in);
    k_out<<<T_STEPS / 32, 128>>>(w_out, b_out, out);
}